// round 4
// baseline (speedup 1.0000x reference)
#include <cuda_runtime.h>
#include <cuda_bf16.h>

#define N_NODES 100000
#define N_EDGES 1600000
#define F 128
#define NB_SCAN 98            // ceil(100000/1024)

typedef unsigned long long u64;

// ---------------- scratch (static __device__, no allocation) ----------------
__device__ int   g_deg_out_i[N_NODES];
__device__ int   g_deg_in_i[N_NODES];
__device__ float g_rs_out[N_NODES];
__device__ float g_rs_in[N_NODES];
__device__ int   g_rowp[N_NODES + 1];     // CSR row pointers (by dst)
__device__ int   g_cursor[N_NODES];       // fill cursors
__device__ int   g_csr[N_EDGES];          // src indices grouped by dst
__device__ int   g_bsum[NB_SCAN];
__device__ int   g_boff[NB_SCAN];
__device__ float g_y[(size_t)N_NODES * 2];

// ---------------- packed fp32x2 helpers (Blackwell paired-FP32 pipe) ---------
__device__ __forceinline__ u64 pack2(float x, float y) {
    u64 r; asm("mov.b64 %0,{%1,%2};" : "=l"(r) : "f"(x), "f"(y)); return r;
}
__device__ __forceinline__ void unpack2(u64 v, float& x, float& y) {
    asm("mov.b64 {%0,%1},%2;" : "=f"(x), "=f"(y) : "l"(v));
}
__device__ __forceinline__ u64 fma2(u64 a, u64 b, u64 c) {
    u64 d; asm("fma.rn.f32x2 %0,%1,%2,%3;" : "=l"(d) : "l"(a), "l"(b), "l"(c)); return d;
}
__device__ __forceinline__ u64 mul2(u64 a, u64 b) {
    u64 d; asm("mul.rn.f32x2 %0,%1,%2;" : "=l"(d) : "l"(a), "l"(b)); return d;
}

// ---------------- zero counters ----------------------------------------------
__global__ void k_zero() {
    int i = blockIdx.x * blockDim.x + threadIdx.x;
    if (i < N_NODES) { g_deg_out_i[i] = 0; g_deg_in_i[i] = 0; }
}

// ---------------- degrees (int histogram, 2 edges/thread) --------------------
__global__ void k_deg(const int2* __restrict__ src2, const int2* __restrict__ dst2) {
    int i = blockIdx.x * blockDim.x + threadIdx.x;
    if (i < N_EDGES / 2) {
        int2 s = src2[i], d = dst2[i];
        atomicAdd(&g_deg_out_i[s.x], 1);
        atomicAdd(&g_deg_out_i[s.y], 1);
        atomicAdd(&g_deg_in_i[d.x], 1);
        atomicAdd(&g_deg_in_i[d.y], 1);
    }
}

// ---------------- block scan of deg_in (warp-shuffle) + rs -------------------
__global__ void k_scan_block() {
    __shared__ int wsum[32];
    int tid = threadIdx.x, lane = tid & 31, wid = tid >> 5;
    int gid = blockIdx.x * 1024 + tid;
    int v = (gid < N_NODES) ? g_deg_in_i[gid] : 0;
    int x = v;
    #pragma unroll
    for (int off = 1; off < 32; off <<= 1) {
        int t = __shfl_up_sync(0xffffffffu, x, off);
        if (lane >= off) x += t;
    }
    if (lane == 31) wsum[wid] = x;
    __syncthreads();
    if (wid == 0) {
        int s = wsum[lane];
        #pragma unroll
        for (int off = 1; off < 32; off <<= 1) {
            int t = __shfl_up_sync(0xffffffffu, s, off);
            if (lane >= off) s += t;
        }
        wsum[lane] = s;
    }
    __syncthreads();
    int inc = x + (wid ? wsum[wid - 1] : 0);
    if (gid < N_NODES) {
        g_rowp[gid + 1] = inc;                         // inclusive, pre-offset
        g_rs_in[gid]  = rsqrtf(fmaxf((float)v, 1.0f));
        g_rs_out[gid] = rsqrtf(fmaxf((float)g_deg_out_i[gid], 1.0f));
    }
    if (tid == 1023) g_bsum[blockIdx.x] = inc;
}

__global__ void k_scan_sums() {
    __shared__ int s[128];
    int tid = threadIdx.x;
    int v = (tid < NB_SCAN) ? g_bsum[tid] : 0;
    s[tid] = v; __syncthreads();
    #pragma unroll
    for (int off = 1; off < 128; off <<= 1) {
        int t = (tid >= off) ? s[tid - off] : 0;
        __syncthreads();
        s[tid] += t;
        __syncthreads();
    }
    if (tid < NB_SCAN) g_boff[tid] = s[tid] - v;       // exclusive
}

__global__ void k_scan_add() {
    int gid = blockIdx.x * blockDim.x + threadIdx.x;
    if (gid < N_NODES) {
        int v = g_rowp[gid + 1] + g_boff[gid >> 10];
        g_rowp[gid + 1] = v;
        if (gid + 1 < N_NODES) g_cursor[gid + 1] = v;
        if (gid == 0) { g_rowp[0] = 0; g_cursor[0] = 0; }
    }
}

// ---------------- CSR bucket fill (2 edges/thread) ---------------------------
__global__ void k_fill(const int2* __restrict__ src2, const int2* __restrict__ dst2) {
    int i = blockIdx.x * blockDim.x + threadIdx.x;
    if (i < N_EDGES / 2) {
        int2 s = src2[i], d = dst2[i];
        int p0 = atomicAdd(&g_cursor[d.x], 1);
        g_csr[p0] = s.x;
        int p1 = atomicAdd(&g_cursor[d.y], 1);
        g_csr[p1] = s.y;
    }
}

// ---------------- fused layer-1: gather + W1 GEMM + relu + W2 -> y -----------
__global__ void __launch_bounds__(256) k_fused1(const ulonglong2* __restrict__ x2,
                                                const float* __restrict__ W1,
                                                const float* __restrict__ b1,
                                                const float* __restrict__ W2) {
    extern __shared__ float smem[];
    float4*     Ws   = (float4*)smem;                   // 4096 float4: W1[k][c]
    ulonglong2* Wsu  = (ulonglong2*)smem;               // same bytes, packed view
    float4*     b1s4 = (float4*)(smem + 16384);         // 32 float4
    float2*     W2s  = (float2*)(smem + 16384 + 128);   // 128 float2

    int tid = threadIdx.x;
    const float4* W14 = (const float4*)W1;
    #pragma unroll
    for (int i = 0; i < 16; i++) Ws[tid + i * 256] = W14[tid + i * 256];
    if (tid < 32)  b1s4[tid] = ((const float4*)b1)[tid];
    if (tid < 128) W2s[tid]  = ((const float2*)W2)[tid];
    __syncthreads();

    int warp = tid >> 5, lane = tid & 31;
    int i0 = blockIdx.x * 32 + warp * 4;                // 3125 * 32 = 100000

    // --- gather: a[m] = rs_in * sum x[src]*rs_out[src] (packed fp32x2) ---
    float4 a[4];
    #pragma unroll
    for (int m = 0; m < 4; m++) {
        int node = i0 + m;
        int beg = __ldg(&g_rowp[node]), end = __ldg(&g_rowp[node + 1]);
        u64 axy = 0, azw = 0;                           // +0.0 packed
        int e = beg;
        for (; e + 4 <= end; e += 4) {
            int s0 = __ldg(&g_csr[e]),     s1 = __ldg(&g_csr[e + 1]);
            int s2 = __ldg(&g_csr[e + 2]), s3 = __ldg(&g_csr[e + 3]);
            float c0 = __ldg(&g_rs_out[s0]), c1 = __ldg(&g_rs_out[s1]);
            float c2 = __ldg(&g_rs_out[s2]), c3 = __ldg(&g_rs_out[s3]);
            ulonglong2 v0 = x2[s0 * 32 + lane];
            ulonglong2 v1 = x2[s1 * 32 + lane];
            ulonglong2 v2 = x2[s2 * 32 + lane];
            ulonglong2 v3 = x2[s3 * 32 + lane];
            u64 cc0 = pack2(c0, c0), cc1 = pack2(c1, c1);
            u64 cc2 = pack2(c2, c2), cc3 = pack2(c3, c3);
            axy = fma2(v0.x, cc0, axy); azw = fma2(v0.y, cc0, azw);
            axy = fma2(v1.x, cc1, axy); azw = fma2(v1.y, cc1, azw);
            axy = fma2(v2.x, cc2, axy); azw = fma2(v2.y, cc2, azw);
            axy = fma2(v3.x, cc3, axy); azw = fma2(v3.y, cc3, azw);
        }
        for (; e < end; ++e) {
            int s0 = __ldg(&g_csr[e]);
            float c0 = __ldg(&g_rs_out[s0]);
            ulonglong2 v0 = x2[s0 * 32 + lane];
            u64 cc0 = pack2(c0, c0);
            axy = fma2(v0.x, cc0, axy); azw = fma2(v0.y, cc0, azw);
        }
        float ri = g_rs_in[node];
        u64 rr = pack2(ri, ri);
        axy = mul2(axy, rr); azw = mul2(azw, rr);
        unpack2(axy, a[m].x, a[m].y);
        unpack2(azw, a[m].z, a[m].w);
    }

    // --- W1 GEMM: acc[m][lane cols] += x_k * W1[k][cols], packed fp32x2 ---
    u64 accxy[4], acczw[4];
    {
        float4 bb = b1s4[lane];
        u64 bxy = pack2(bb.x, bb.y), bzw = pack2(bb.z, bb.w);
        #pragma unroll
        for (int m = 0; m < 4; m++) { accxy[m] = bxy; acczw[m] = bzw; }
    }

    #pragma unroll 8
    for (int sl = 0; sl < 32; ++sl) {
        #pragma unroll
        for (int j = 0; j < 4; j++) {
            int k = sl * 4 + j;
            ulonglong2 wv = Wsu[k * 32 + lane];
            float x0, x1, x2v, x3;
            if      (j == 0) { x0 = a[0].x; x1 = a[1].x; x2v = a[2].x; x3 = a[3].x; }
            else if (j == 1) { x0 = a[0].y; x1 = a[1].y; x2v = a[2].y; x3 = a[3].y; }
            else if (j == 2) { x0 = a[0].z; x1 = a[1].z; x2v = a[2].z; x3 = a[3].z; }
            else             { x0 = a[0].w; x1 = a[1].w; x2v = a[2].w; x3 = a[3].w; }
            x0  = __shfl_sync(0xffffffffu, x0,  sl);
            x1  = __shfl_sync(0xffffffffu, x1,  sl);
            x2v = __shfl_sync(0xffffffffu, x2v, sl);
            x3  = __shfl_sync(0xffffffffu, x3,  sl);
            u64 xx0 = pack2(x0, x0),   xx1 = pack2(x1, x1);
            u64 xx2 = pack2(x2v, x2v), xx3 = pack2(x3, x3);
            accxy[0] = fma2(wv.x, xx0, accxy[0]); acczw[0] = fma2(wv.y, xx0, acczw[0]);
            accxy[1] = fma2(wv.x, xx1, accxy[1]); acczw[1] = fma2(wv.y, xx1, acczw[1]);
            accxy[2] = fma2(wv.x, xx2, accxy[2]); acczw[2] = fma2(wv.y, xx2, acczw[2]);
            accxy[3] = fma2(wv.x, xx3, accxy[3]); acczw[3] = fma2(wv.y, xx3, acczw[3]);
        }
    }

    // --- relu + W2 (128x2) projection, warp-reduce, *rs_out -> y ---
    float2 w0 = W2s[4 * lane + 0], w1 = W2s[4 * lane + 1];
    float2 w2 = W2s[4 * lane + 2], w3 = W2s[4 * lane + 3];
    float p0[4], p1[4];
    #pragma unroll
    for (int m = 0; m < 4; m++) {
        float h0, h1, h2, h3;
        unpack2(accxy[m], h0, h1);
        unpack2(acczw[m], h2, h3);
        h0 = fmaxf(h0, 0.f); h1 = fmaxf(h1, 0.f);
        h2 = fmaxf(h2, 0.f); h3 = fmaxf(h3, 0.f);
        p0[m] = h0 * w0.x + h1 * w1.x + h2 * w2.x + h3 * w3.x;
        p1[m] = h0 * w0.y + h1 * w1.y + h2 * w2.y + h3 * w3.y;
    }
    #pragma unroll
    for (int off = 16; off; off >>= 1) {
        #pragma unroll
        for (int m = 0; m < 4; m++) {
            p0[m] += __shfl_xor_sync(0xffffffffu, p0[m], off);
            p1[m] += __shfl_xor_sync(0xffffffffu, p1[m], off);
        }
    }
    if (lane == 0) {
        float2* y2 = (float2*)g_y;
        #pragma unroll
        for (int m = 0; m < 4; m++) {
            float ro = g_rs_out[i0 + m];
            y2[i0 + m] = make_float2(p0[m] * ro, p1[m] * ro);
        }
    }
}

// ---------------- layer-2: CSR gather of y + finalize ------------------------
__global__ void k_out(float* __restrict__ out, const float* __restrict__ b2) {
    int i = blockIdx.x * blockDim.x + threadIdx.x;
    if (i >= N_NODES) return;
    int beg = __ldg(&g_rowp[i]), end = __ldg(&g_rowp[i + 1]);
    const float2* y2 = (const float2*)g_y;
    float s0 = 0.f, s1 = 0.f;
    int e = beg;
    for (; e + 2 <= end; e += 2) {
        int a = __ldg(&g_csr[e]), b = __ldg(&g_csr[e + 1]);
        float2 va = y2[a], vb = y2[b];
        s0 += va.x + vb.x;
        s1 += va.y + vb.y;
    }
    if (e < end) {
        float2 va = y2[__ldg(&g_csr[e])];
        s0 += va.x; s1 += va.y;
    }
    float ri = g_rs_in[i];
    ((float2*)out)[i] = make_float2(s0 * ri + __ldg(&b2[0]),
                                    s1 * ri + __ldg(&b2[1]));
}

// ---------------- launch ------------------------------------------------------
extern "C" void kernel_launch(void* const* d_in, const int* in_sizes, int n_in,
                              void* d_out, int out_size) {
    const float* in_feat = (const float*)d_in[0];
    const int*   src     = (const int*)d_in[1];
    const int*   dst     = (const int*)d_in[2];
    const float* W1      = (const float*)d_in[3];
    const float* b1      = (const float*)d_in[4];
    const float* W2      = (const float*)d_in[5];
    const float* b2      = (const float*)d_in[6];
    float*       out     = (float*)d_out;

    const int T = 256;
    const int SMEM_NODE = (16384 + 128 + 256) * (int)sizeof(float); // 67072 B
    cudaFuncSetAttribute(k_fused1, cudaFuncAttributeMaxDynamicSharedMemorySize, SMEM_NODE);

    k_zero<<<(N_NODES + T - 1) / T, T>>>();
    k_deg<<<(N_EDGES / 2 + T - 1) / T, T>>>((const int2*)src, (const int2*)dst);
    k_scan_block<<<NB_SCAN, 1024>>>();
    k_scan_sums<<<1, 128>>>();
    k_scan_add<<<(N_NODES + T - 1) / T, T>>>();
    k_fill<<<(N_EDGES / 2 + T - 1) / T, T>>>((const int2*)src, (const int2*)dst);
    k_fused1<<<N_NODES / 32, T, SMEM_NODE>>>((const ulonglong2*)in_feat, W1, b1, W2);
    k_out<<<(N_NODES + T - 1) / T, T>>>(out, b2);
}

// round 5
// speedup vs baseline: 1.0079x; 1.0079x over previous
#include <cuda_runtime.h>
#include <cuda_fp16.h>

#define N_NODES 100000
#define N_EDGES 1600000
#define F 128
#define NB_SCAN 98            // ceil(100000/1024)

// ---------------- scratch (static __device__, no allocation) ----------------
__device__ int   g_deg_out_i[N_NODES];
__device__ int   g_deg_in_i[N_NODES];
__device__ float g_rs_out[N_NODES];
__device__ float g_rs_in[N_NODES];
__device__ int   g_rowp[N_NODES + 1];     // CSR row pointers (by dst)
__device__ int   g_cursor[N_NODES];       // fill cursors
__device__ int   g_csr[N_EDGES];          // src indices grouped by dst
__device__ int   g_bsum[NB_SCAN];
__device__ int   g_boff[NB_SCAN];
__device__ float g_y[(size_t)N_NODES * 2];
__device__ __align__(16) __half g_xh[(size_t)N_NODES * F];  // fp16(x * rs_out), 25.6 MB

// ---------------- zero counters ----------------------------------------------
__global__ void k_zero() {
    int i = blockIdx.x * blockDim.x + threadIdx.x;
    if (i < N_NODES) { g_deg_out_i[i] = 0; g_deg_in_i[i] = 0; }
}

// ---------------- degrees (int histogram, 2 edges/thread) --------------------
__global__ void k_deg(const int2* __restrict__ src2, const int2* __restrict__ dst2) {
    int i = blockIdx.x * blockDim.x + threadIdx.x;
    if (i < N_EDGES / 2) {
        int2 s = src2[i], d = dst2[i];
        atomicAdd(&g_deg_out_i[s.x], 1);
        atomicAdd(&g_deg_out_i[s.y], 1);
        atomicAdd(&g_deg_in_i[d.x], 1);
        atomicAdd(&g_deg_in_i[d.y], 1);
    }
}

// ---------------- block scan of deg_in (warp-shuffle) + rs -------------------
__global__ void k_scan_block() {
    __shared__ int wsum[32];
    int tid = threadIdx.x, lane = tid & 31, wid = tid >> 5;
    int gid = blockIdx.x * 1024 + tid;
    int v = (gid < N_NODES) ? g_deg_in_i[gid] : 0;
    int x = v;
    #pragma unroll
    for (int off = 1; off < 32; off <<= 1) {
        int t = __shfl_up_sync(0xffffffffu, x, off);
        if (lane >= off) x += t;
    }
    if (lane == 31) wsum[wid] = x;
    __syncthreads();
    if (wid == 0) {
        int s = wsum[lane];
        #pragma unroll
        for (int off = 1; off < 32; off <<= 1) {
            int t = __shfl_up_sync(0xffffffffu, s, off);
            if (lane >= off) s += t;
        }
        wsum[lane] = s;
    }
    __syncthreads();
    int inc = x + (wid ? wsum[wid - 1] : 0);
    if (gid < N_NODES) {
        g_rowp[gid + 1] = inc;                         // inclusive, pre-offset
        g_rs_in[gid]  = rsqrtf(fmaxf((float)v, 1.0f));
        g_rs_out[gid] = rsqrtf(fmaxf((float)g_deg_out_i[gid], 1.0f));
    }
    if (tid == 1023) g_bsum[blockIdx.x] = inc;
}

__global__ void k_scan_sums() {
    __shared__ int s[128];
    int tid = threadIdx.x;
    int v = (tid < NB_SCAN) ? g_bsum[tid] : 0;
    s[tid] = v; __syncthreads();
    #pragma unroll
    for (int off = 1; off < 128; off <<= 1) {
        int t = (tid >= off) ? s[tid - off] : 0;
        __syncthreads();
        s[tid] += t;
        __syncthreads();
    }
    if (tid < NB_SCAN) g_boff[tid] = s[tid] - v;       // exclusive
}

__global__ void k_scan_add() {
    int gid = blockIdx.x * blockDim.x + threadIdx.x;
    if (gid < N_NODES) {
        int v = g_rowp[gid + 1] + g_boff[gid >> 10];
        g_rowp[gid + 1] = v;
        if (gid + 1 < N_NODES) g_cursor[gid + 1] = v;
        if (gid == 0) { g_rowp[0] = 0; g_cursor[0] = 0; }
    }
}

// ---------------- x -> fp16(x * rs_out) --------------------------------------
// Needs rs_out (after k_scan_block). idx over N_NODES*64 half2 pairs.
__global__ void k_tohalf(const float2* __restrict__ x2) {
    int idx = blockIdx.x * blockDim.x + threadIdx.x;
    if (idx < N_NODES * 64) {
        int node = idx >> 6;                 // 64 float2 per 128-feat row
        float c = g_rs_out[node];
        float2 v = x2[idx];
        ((__half2*)g_xh)[idx] = __floats2half2_rn(v.x * c, v.y * c);
    }
}

// ---------------- CSR bucket fill (2 edges/thread) ---------------------------
__global__ void k_fill(const int2* __restrict__ src2, const int2* __restrict__ dst2) {
    int i = blockIdx.x * blockDim.x + threadIdx.x;
    if (i < N_EDGES / 2) {
        int2 s = src2[i], d = dst2[i];
        int p0 = atomicAdd(&g_cursor[d.x], 1);
        g_csr[p0] = s.x;
        int p1 = atomicAdd(&g_cursor[d.y], 1);
        g_csr[p1] = s.y;
    }
}

// ---------------- fused layer-1: fp16 gather + W1 GEMM + relu + W2 -> y ------
// Warp handles 4 nodes: a[m] = rs_in * sum_{e in in(m)} xh[src_e]  (fp32 accum)
// Lane owns features 4l..4l+3 (one LDG.64 of 4 halves per edge).
__global__ void __launch_bounds__(256) k_fused1(const float* __restrict__ W1,
                                                const float* __restrict__ b1,
                                                const float* __restrict__ W2) {
    extern __shared__ float smem[];
    float4* Ws   = (float4*)smem;                  // 4096 float4: W1[k][c]
    float4* b1s4 = (float4*)(smem + 16384);        // 32 float4
    float2* W2s  = (float2*)(smem + 16384 + 128);  // 128 float2

    int tid = threadIdx.x;
    const float4* W14 = (const float4*)W1;
    #pragma unroll
    for (int i = 0; i < 16; i++) Ws[tid + i * 256] = W14[tid + i * 256];
    if (tid < 32)  b1s4[tid] = ((const float4*)b1)[tid];
    if (tid < 128) W2s[tid]  = ((const float2*)W2)[tid];
    __syncthreads();

    int warp = tid >> 5, lane = tid & 31;
    int i0 = blockIdx.x * 32 + warp * 4;           // 3125 * 32 = 100000

    const uint2* xh2 = (const uint2*)g_xh;         // 8 B = 4 halves per lane

    float4 a[4];
    #pragma unroll
    for (int m = 0; m < 4; m++) {
        int node = i0 + m;
        int beg = __ldg(&g_rowp[node]), end = __ldg(&g_rowp[node + 1]);
        float4 acc = make_float4(0.f, 0.f, 0.f, 0.f);
        int e = beg;
        for (; e + 4 <= end; e += 4) {
            int s0 = __ldg(&g_csr[e]),     s1 = __ldg(&g_csr[e + 1]);
            int s2 = __ldg(&g_csr[e + 2]), s3 = __ldg(&g_csr[e + 3]);
            uint2 v0 = xh2[s0 * 32 + lane];
            uint2 v1 = xh2[s1 * 32 + lane];
            uint2 v2 = xh2[s2 * 32 + lane];
            uint2 v3 = xh2[s3 * 32 + lane];
            float2 f;
            f = __half22float2(*(__half2*)&v0.x); acc.x += f.x; acc.y += f.y;
            f = __half22float2(*(__half2*)&v0.y); acc.z += f.x; acc.w += f.y;
            f = __half22float2(*(__half2*)&v1.x); acc.x += f.x; acc.y += f.y;
            f = __half22float2(*(__half2*)&v1.y); acc.z += f.x; acc.w += f.y;
            f = __half22float2(*(__half2*)&v2.x); acc.x += f.x; acc.y += f.y;
            f = __half22float2(*(__half2*)&v2.y); acc.z += f.x; acc.w += f.y;
            f = __half22float2(*(__half2*)&v3.x); acc.x += f.x; acc.y += f.y;
            f = __half22float2(*(__half2*)&v3.y); acc.z += f.x; acc.w += f.y;
        }
        for (; e < end; ++e) {
            int s0 = __ldg(&g_csr[e]);
            uint2 v0 = xh2[s0 * 32 + lane];
            float2 f;
            f = __half22float2(*(__half2*)&v0.x); acc.x += f.x; acc.y += f.y;
            f = __half22float2(*(__half2*)&v0.y); acc.z += f.x; acc.w += f.y;
        }
        float ri = g_rs_in[node];
        a[m] = make_float4(acc.x * ri, acc.y * ri, acc.z * ri, acc.w * ri);
    }

    float4 acc[4];
    #pragma unroll
    for (int m = 0; m < 4; m++) acc[m] = b1s4[lane];

    #pragma unroll 8
    for (int sl = 0; sl < 32; ++sl) {
        #pragma unroll
        for (int j = 0; j < 4; j++) {
            int k = sl * 4 + j;
            float4 wv = Ws[k * 32 + lane];
            float x0, x1, x2, x3;
            if      (j == 0) { x0 = a[0].x; x1 = a[1].x; x2 = a[2].x; x3 = a[3].x; }
            else if (j == 1) { x0 = a[0].y; x1 = a[1].y; x2 = a[2].y; x3 = a[3].y; }
            else if (j == 2) { x0 = a[0].z; x1 = a[1].z; x2 = a[2].z; x3 = a[3].z; }
            else             { x0 = a[0].w; x1 = a[1].w; x2 = a[2].w; x3 = a[3].w; }
            x0 = __shfl_sync(0xffffffffu, x0, sl);
            x1 = __shfl_sync(0xffffffffu, x1, sl);
            x2 = __shfl_sync(0xffffffffu, x2, sl);
            x3 = __shfl_sync(0xffffffffu, x3, sl);
            acc[0].x += x0 * wv.x; acc[0].y += x0 * wv.y; acc[0].z += x0 * wv.z; acc[0].w += x0 * wv.w;
            acc[1].x += x1 * wv.x; acc[1].y += x1 * wv.y; acc[1].z += x1 * wv.z; acc[1].w += x1 * wv.w;
            acc[2].x += x2 * wv.x; acc[2].y += x2 * wv.y; acc[2].z += x2 * wv.z; acc[2].w += x2 * wv.w;
            acc[3].x += x3 * wv.x; acc[3].y += x3 * wv.y; acc[3].z += x3 * wv.z; acc[3].w += x3 * wv.w;
        }
    }

    float2 w0 = W2s[4 * lane + 0], w1 = W2s[4 * lane + 1];
    float2 w2 = W2s[4 * lane + 2], w3 = W2s[4 * lane + 3];
    float p0[4], p1[4];
    #pragma unroll
    for (int m = 0; m < 4; m++) {
        float h0 = fmaxf(acc[m].x, 0.f), h1 = fmaxf(acc[m].y, 0.f);
        float h2 = fmaxf(acc[m].z, 0.f), h3 = fmaxf(acc[m].w, 0.f);
        p0[m] = h0 * w0.x + h1 * w1.x + h2 * w2.x + h3 * w3.x;
        p1[m] = h0 * w0.y + h1 * w1.y + h2 * w2.y + h3 * w3.y;
    }
    #pragma unroll
    for (int off = 16; off; off >>= 1) {
        #pragma unroll
        for (int m = 0; m < 4; m++) {
            p0[m] += __shfl_xor_sync(0xffffffffu, p0[m], off);
            p1[m] += __shfl_xor_sync(0xffffffffu, p1[m], off);
        }
    }
    if (lane == 0) {
        float2* y2 = (float2*)g_y;
        #pragma unroll
        for (int m = 0; m < 4; m++) {
            float ro = g_rs_out[i0 + m];
            y2[i0 + m] = make_float2(p0[m] * ro, p1[m] * ro);
        }
    }
}

// ---------------- layer-2: CSR gather of y + finalize ------------------------
__global__ void k_out(float* __restrict__ out, const float* __restrict__ b2) {
    int i = blockIdx.x * blockDim.x + threadIdx.x;
    if (i >= N_NODES) return;
    int beg = __ldg(&g_rowp[i]), end = __ldg(&g_rowp[i + 1]);
    const float2* y2 = (const float2*)g_y;
    float s0 = 0.f, s1 = 0.f;
    int e = beg;
    for (; e + 2 <= end; e += 2) {
        int a = __ldg(&g_csr[e]), b = __ldg(&g_csr[e + 1]);
        float2 va = y2[a], vb = y2[b];
        s0 += va.x + vb.x;
        s1 += va.y + vb.y;
    }
    if (e < end) {
        float2 va = y2[__ldg(&g_csr[e])];
        s0 += va.x; s1 += va.y;
    }
    float ri = g_rs_in[i];
    ((float2*)out)[i] = make_float2(s0 * ri + __ldg(&b2[0]),
                                    s1 * ri + __ldg(&b2[1]));
}

// ---------------- launch ------------------------------------------------------
extern "C" void kernel_launch(void* const* d_in, const int* in_sizes, int n_in,
                              void* d_out, int out_size) {
    const float* in_feat = (const float*)d_in[0];
    const int*   src     = (const int*)d_in[1];
    const int*   dst     = (const int*)d_in[2];
    const float* W1      = (const float*)d_in[3];
    const float* b1      = (const float*)d_in[4];
    const float* W2      = (const float*)d_in[5];
    const float* b2      = (const float*)d_in[6];
    float*       out     = (float*)d_out;

    const int T = 256;
    const int SMEM_NODE = (16384 + 128 + 256) * (int)sizeof(float); // 67072 B
    cudaFuncSetAttribute(k_fused1, cudaFuncAttributeMaxDynamicSharedMemorySize, SMEM_NODE);

    k_zero<<<(N_NODES + T - 1) / T, T>>>();
    k_deg<<<(N_EDGES / 2 + T - 1) / T, T>>>((const int2*)src, (const int2*)dst);
    k_scan_block<<<NB_SCAN, 1024>>>();
    k_tohalf<<<(N_NODES * 64 + T - 1) / T, T>>>((const float2*)in_feat);
    k_scan_sums<<<1, 128>>>();
    k_scan_add<<<(N_NODES + T - 1) / T, T>>>();
    k_fill<<<(N_EDGES / 2 + T - 1) / T, T>>>((const int2*)src, (const int2*)dst);
    k_fused1<<<N_NODES / 32, T, SMEM_NODE>>>(W1, b1, W2);
    k_out<<<(N_NODES + T - 1) / T, T>>>(out, b2);
}